// round 5
// baseline (speedup 1.0000x reference)
#include <cuda_runtime.h>

// MixedActivation: cols with (col % 6) < 3 -> x*x ; else PReLU with slope
// prelu_a[(col % 6) - 3]. x is [1000000, 48] fp32, contiguous.
//
// R5: 256-bit global loads/stores (ld/st.global.v8.f32, sm_100a) to halve
// transaction count and lengthen DRAM bursts. 48M floats = 6M float8;
// TPB=128 x UNROLL=3 = 384 float8/block -> grid = 15625 EXACT, so no bounds
// checks anywhere. For float8 index j (cols 8j..8j+7), phase
// m0 = (8j) mod 6 = 2*(j mod 3); component c has m = (m0+c) mod 6.

#define UNROLL 3
#define TPB 128

__device__ __forceinline__ void ldg256_cs(const float* p, float* x) {
    asm volatile(
        "ld.global.cs.v8.f32 {%0,%1,%2,%3,%4,%5,%6,%7}, [%8];"
        : "=f"(x[0]), "=f"(x[1]), "=f"(x[2]), "=f"(x[3]),
          "=f"(x[4]), "=f"(x[5]), "=f"(x[6]), "=f"(x[7])
        : "l"(p));
}

__device__ __forceinline__ void stg256_cs(float* p, const float* x) {
    asm volatile(
        "st.global.cs.v8.f32 [%0], {%1,%2,%3,%4,%5,%6,%7,%8};"
        :: "l"(p),
           "f"(x[0]), "f"(x[1]), "f"(x[2]), "f"(x[3]),
           "f"(x[4]), "f"(x[5]), "f"(x[6]), "f"(x[7])
        : "memory");
}

__global__ void __launch_bounds__(TPB)
mixed_act_kernel(const float* __restrict__ in,
                 const float* __restrict__ pa,
                 float* __restrict__ out) {
    const int base = blockIdx.x * (TPB * UNROLL) + threadIdx.x;  // float8 index

    const float a0 = __ldg(pa + 0);
    const float a1 = __ldg(pa + 1);
    const float a2 = __ldg(pa + 2);

    // Front-batch all loads: 3 independent 256-bit loads per thread.
    float v[UNROLL][8];
#pragma unroll
    for (int k = 0; k < UNROLL; k++) {
        int j = base + k * TPB;
        ldg256_cs(in + (size_t)j * 8, v[k]);
    }

#pragma unroll
    for (int k = 0; k < UNROLL; k++) {
        int j = base + k * TPB;
        int m0 = 2 * (j % 3);        // (8j) mod 6 : 0, 2, or 4

        float o[8];
#pragma unroll
        for (int c = 0; c < 8; c++) {
            int m = m0 + c;          // 0..11
            if (m >= 6) m -= 6;      // m = col % 6
            float x = v[k][c];
            float a = (m == 3) ? a0 : ((m == 4) ? a1 : a2);
            float sq = x * x;
            float pr = fmaxf(x, 0.0f) + a * fminf(x, 0.0f);
            o[c] = (m < 3) ? sq : pr;
        }
        stg256_cs(out + (size_t)j * 8, o);
    }
}

extern "C" void kernel_launch(void* const* d_in, const int* in_sizes, int n_in,
                              void* d_out, int out_size) {
    const float* x  = (const float*)d_in[0];
    const float* pa = (const float*)d_in[1];
    float* out = (float*)d_out;

    int n8 = out_size / 8;                          // 6,000,000 float8s
    int blocks = n8 / (TPB * UNROLL);               // exactly 15625
    mixed_act_kernel<<<blocks, TPB>>>(x, pa, out);
}

// round 6
// speedup vs baseline: 1.0089x; 1.0089x over previous
#include <cuda_runtime.h>

// MixedActivation: cols with (col % 6) < 3 -> x*x ; else PReLU with slope
// prelu_a[(col % 6) - 3]. x is [1000000, 48] fp32, contiguous.
//
// R6: ceiling-locked variant. Measurements R2/R4/R5 showed 6.1 TB/s DRAM
// regardless of MLP (3/4/8) or transaction width (128/256-bit) -> the kernel
// is LTS-capped (384 MB through L2 at ~7.1 TB/s = chip LTS ceiling). This
// round just removes all dead instructions: TPB=256 x UNROLL=3 float4 = 768
// float4/block, and 12M float4 / 768 = 15625 blocks EXACTLY -> zero bounds
// checks, zero predicates. Streaming hints on both sides.
//
// Phase logic: float4 index i covers cols 4i..4i+3; (4i) mod 6 depends only
// on r = i % 3: r=0 -> mods {0,1,2,3}, r=1 -> {4,5,0,1}, r=2 -> {2,3,4,5}.

#define UNROLL 3
#define TPB 256

__global__ void __launch_bounds__(TPB)
mixed_act_kernel(const float4* __restrict__ in,
                 const float* __restrict__ pa,
                 float4* __restrict__ out) {
    const int base = blockIdx.x * (TPB * UNROLL) + threadIdx.x;

    const float a0 = __ldg(pa + 0);
    const float a1 = __ldg(pa + 1);
    const float a2 = __ldg(pa + 2);

    // Front-batch all loads: 3 independent LDG.128 in flight per thread.
    float4 v[UNROLL];
#pragma unroll
    for (int k = 0; k < UNROLL; k++)
        v[k] = __ldcs(&in[base + k * TPB]);

#pragma unroll
    for (int k = 0; k < UNROLL; k++) {
        const int i = base + k * TPB;
        int r = i % 3;       // phase of this float4 within the 6-col pattern
        int m0 = r * 4;      // (col % 12) of component 0; reduce mod 6 per c

        float x[4] = {v[k].x, v[k].y, v[k].z, v[k].w};
        float o[4];
#pragma unroll
        for (int c = 0; c < 4; c++) {
            int m = m0 + c;
            if (m >= 6) m -= 6;                   // m = col % 6 (0..5)
            float a = (m == 3) ? a0 : ((m == 4) ? a1 : a2);
            float sq = x[c] * x[c];
            float pr = fmaxf(x[c], 0.0f) + a * fminf(x[c], 0.0f);
            o[c] = (m < 3) ? sq : pr;             // predicated select
        }
        __stcs(&out[i], make_float4(o[0], o[1], o[2], o[3]));
    }
}

extern "C" void kernel_launch(void* const* d_in, const int* in_sizes, int n_in,
                              void* d_out, int out_size) {
    const float* x  = (const float*)d_in[0];
    const float* pa = (const float*)d_in[1];
    float* out = (float*)d_out;

    int n4 = out_size / 4;                   // 12,000,000 float4s
    int blocks = n4 / (TPB * UNROLL);        // exactly 15625
    mixed_act_kernel<<<blocks, TPB>>>((const float4*)x, pa, (float4*)out);
}